// round 3
// baseline (speedup 1.0000x reference)
#include <cuda_runtime.h>
#include <cstdint>

#define THREADS 256
#define HID 256
#define CHUNK 32

#define HS_FLOATS (64 * 256)            // activations
#define WS_FLOATS (2 * CHUNK * 256)     // weight double buffer
#define A0_FLOATS (64 * 64)             // PE input (63 padded to 64), reused as scratch
#define SMEM_BYTES ((HS_FLOATS + WS_FLOATS + A0_FLOATS) * 4)

__device__ __forceinline__ uint32_t sm_u32(const void* p) {
    return (uint32_t)__cvta_generic_to_shared(p);
}

__device__ __forceinline__ void cp_chunk(float* dst, const float* __restrict__ src, int tid) {
    // one CHUNK x 256 fp32 tile = 2048 float4 slots; 8 per thread
#pragma unroll
    for (int s = 0; s < 8; ++s) {
        int slot = tid + s * THREADS;
        asm volatile("cp.async.cg.shared.global [%0], [%1], 16;\n"
                     :: "r"(sm_u32(dst + slot * 4)), "l"(src + slot * 4) : "memory");
    }
}

// M=64 x N=256 register-tiled FMA over one 32-wide K chunk.
// Thread (tm = tid>>5, tn = tid&31) owns rows [tm*8, tm*8+8) and columns
// {tn*4..tn*4+3} U {128+tn*4..128+tn*4+3}  -> conflict-free LDS.128 on W rows,
// warp-uniform (broadcast) LDS.128 on A rows.
template<int AS>
__device__ __forceinline__ void mma_chunk(float (&acc)[8][8],
        const float* __restrict__ A, int kbase,
        const float* __restrict__ Wb, int r0, int n0a, int n0b) {
#pragma unroll
    for (int kk = 0; kk < CHUNK; kk += 4) {
        float4 a4[8];
#pragma unroll
        for (int i = 0; i < 8; ++i)
            a4[i] = *(const float4*)(A + (r0 + i) * AS + kbase + kk);
#pragma unroll
        for (int u = 0; u < 4; ++u) {
            const float* wr = Wb + (kk + u) * HID;
            float4 w0 = *(const float4*)(wr + n0a);
            float4 w1 = *(const float4*)(wr + n0b);
            float wv[8] = {w0.x, w0.y, w0.z, w0.w, w1.x, w1.y, w1.z, w1.w};
#pragma unroll
            for (int i = 0; i < 8; ++i) {
                float av = (u == 0) ? a4[i].x : (u == 1) ? a4[i].y
                         : (u == 2) ? a4[i].z : a4[i].w;
#pragma unroll
                for (int j = 0; j < 8; ++j)
                    acc[i][j] = fmaf(av, wv[j], acc[i][j]);
            }
        }
    }
}

__device__ __forceinline__ void finish_layer(float (&acc)[8][8],
        const float* __restrict__ bg, float* Out, int r0, int n0a, int n0b) {
    float4 bb0 = *(const float4*)(bg + n0a);
    float4 bb1 = *(const float4*)(bg + n0b);
    float bs[8] = {bb0.x, bb0.y, bb0.z, bb0.w, bb1.x, bb1.y, bb1.z, bb1.w};
    __syncthreads();  // all reads of the input activation buffer are done
#pragma unroll
    for (int i = 0; i < 8; ++i) {
        float4 v0, v1;
        v0.x = fmaxf(acc[i][0] + bs[0], 0.f);
        v0.y = fmaxf(acc[i][1] + bs[1], 0.f);
        v0.z = fmaxf(acc[i][2] + bs[2], 0.f);
        v0.w = fmaxf(acc[i][3] + bs[3], 0.f);
        v1.x = fmaxf(acc[i][4] + bs[4], 0.f);
        v1.y = fmaxf(acc[i][5] + bs[5], 0.f);
        v1.z = fmaxf(acc[i][6] + bs[6], 0.f);
        v1.w = fmaxf(acc[i][7] + bs[7], 0.f);
        *(float4*)(Out + (r0 + i) * HID + n0a) = v0;
        *(float4*)(Out + (r0 + i) * HID + n0b) = v1;
    }
    __syncthreads();
}

// 256x256 layer with cp.async double-buffered weight streaming, in-place on Hs.
__device__ __forceinline__ void big_layer(const float* __restrict__ Wg,
        const float* __restrict__ bg, float* Hs, float* Ws,
        int r0, int n0a, int n0b, int tid) {
    float acc[8][8];
#pragma unroll
    for (int i = 0; i < 8; ++i)
#pragma unroll
        for (int j = 0; j < 8; ++j) acc[i][j] = 0.f;

    cp_chunk(Ws, Wg, tid);
    asm volatile("cp.async.commit_group;\n" ::: "memory");
#pragma unroll 1
    for (int c = 0; c < 8; ++c) {
        asm volatile("cp.async.wait_group 0;\n" ::: "memory");
        __syncthreads();                          // chunk c visible to all threads
        if (c < 7) {
            cp_chunk(Ws + ((c + 1) & 1) * (CHUNK * HID),
                     Wg + (c + 1) * (CHUNK * HID), tid);
            asm volatile("cp.async.commit_group;\n" ::: "memory");
        }
        mma_chunk<HID>(acc, Hs, c * CHUNK, Ws + (c & 1) * (CHUNK * HID),
                       r0, n0a, n0b);
    }
    finish_layer(acc, bg, Hs, r0, n0a, n0b);
}

__global__ void __launch_bounds__(THREADS, 1)
nerf_fused_kernel(const float* __restrict__ origins,
                  const float* __restrict__ dirs,
                  const float* __restrict__ nearp,
                  const float* __restrict__ farp,
                  const float* __restrict__ W0, const float* __restrict__ b0,
                  const float* __restrict__ W1, const float* __restrict__ b1,
                  const float* __restrict__ W2, const float* __restrict__ b2,
                  const float* __restrict__ W3, const float* __restrict__ b3,
                  float* __restrict__ out) {
    extern __shared__ float sm[];
    float* Hs  = sm;                           // 64 x 256
    float* Ws  = sm + HS_FLOATS;               // 2 x 32 x 256
    float* A0s = sm + HS_FLOATS + WS_FLOATS;   // 64 x 64 (63 valid + zero pad)

    const int tid = threadIdx.x;
    const int ray = blockIdx.x;
    const int tm = tid >> 5, tn = tid & 31;
    const int r0 = tm * 8;
    const int n0a = tn * 4;
    const int n0b = 128 + tn * 4;

    const float nearv = *nearp, farv = *farp;
    const float step = (farv - nearv) * (1.0f / 64.0f);

    // ---- sample locations (faithful midpoint: b[s] + b[s+1]/2) into A0s cols 0..2
    if (tid < 192) {
        int s = tid / 3, d = tid % 3;
        float bs  = nearv + step * (float)s;
        float bs1 = nearv + step * (float)(s + 1);
        float mid = bs + 0.5f * bs1;
        A0s[s * 64 + d] = origins[ray * 3 + d] + mid * dirs[ray * 3 + d];
    }
    if (tid < 64) A0s[tid * 64 + 63] = 0.f;     // zero pad col 63
    __syncthreads();

    // ---- positional encoding: feature 3 + f*6 + j ; j<3 sin, j>=3 cos, dim = j%3
    for (int idx = tid; idx < 64 * 60; idx += THREADS) {
        int s = idx / 60, e = idx % 60;
        int f = e / 6, j = e % 6;
        float v = A0s[s * 64 + (j % 3)] * exp2f((float)f);
        A0s[s * 64 + 3 + e] = (j < 3) ? sinf(v) : cosf(v);
    }
    __syncthreads();

    // ---- layer 0: A0s[64x64] @ W0[63x256] (row 63 zero-filled)
    {
        float acc[8][8];
#pragma unroll
        for (int i = 0; i < 8; ++i)
#pragma unroll
            for (int j = 0; j < 8; ++j) acc[i][j] = 0.f;
#pragma unroll 1
        for (int c = 0; c < 2; ++c) {
            __syncthreads();
#pragma unroll
            for (int s = 0; s < 8; ++s) {
                int slot = tid + s * THREADS;           // 0..2047
                int row = slot >> 6, col4 = slot & 63;
                int gk = c * CHUNK + row;
                float4 v = make_float4(0.f, 0.f, 0.f, 0.f);
                if (gk < 63) v = *(const float4*)(W0 + gk * HID + col4 * 4);
                *(float4*)(Ws + slot * 4) = v;
            }
            __syncthreads();
            mma_chunk<64>(acc, A0s, c * CHUNK, Ws, r0, n0a, n0b);
        }
        finish_layer(acc, b0, Hs, r0, n0a, n0b);
    }

    // ---- layers 1, 2: 256x256, in-place on Hs
    big_layer(W1, b1, Hs, Ws, r0, n0a, n0b, tid);
    big_layer(W2, b2, Hs, Ws, r0, n0a, n0b, tid);

    // ---- layer 3: Hs[64x256] @ W3[256x4] + b3 -> A0s[0..255] (p*4+c)
    for (int i = tid; i < 1024; i += THREADS) Ws[i] = W3[i];
    __syncthreads();
    {
        int p = tid >> 2, cc = tid & 3;
        float a3 = b3[cc];
        const float* hrow = Hs + p * HID;
#pragma unroll 8
        for (int k = 0; k < HID; k += 4) {
            float4 h4 = *(const float4*)(hrow + k);
            a3 = fmaf(h4.x, Ws[(k + 0) * 4 + cc], a3);
            a3 = fmaf(h4.y, Ws[(k + 1) * 4 + cc], a3);
            a3 = fmaf(h4.z, Ws[(k + 2) * 4 + cc], a3);
            a3 = fmaf(h4.w, Ws[(k + 3) * 4 + cc], a3);
        }
        A0s[tid] = a3;
    }
    __syncthreads();

    // ---- alpha compositing
    float* out4s  = A0s;          // 256 floats
    float* alphas = A0s + 256;    // 64
    float* rgbs   = A0s + 320;    // 192
    if (tid < 64) {
        float sig = fmaxf(out4s[tid * 4 + 3], 0.f);
        float d0 = (nearv + step * (float)(tid + 1)) - (nearv + step * (float)tid);
        alphas[tid] = 1.f - expf(-sig * d0);
    }
    if (tid < 192) {
        int s = tid / 3, c = tid % 3;
        float x = out4s[s * 4 + c];
        rgbs[tid] = 1.f / (1.f + expf(-x));
    }
    __syncthreads();
    if (tid < 3) {
        float T = 1.f, accum = 0.f;
#pragma unroll 1
        for (int s = 0; s < 64; ++s) {
            float a = alphas[s];
            accum += T * a * rgbs[s * 3 + tid];
            T *= (1.f - a);
        }
        out[ray * 3 + tid] = accum;
    }
}

extern "C" void kernel_launch(void* const* d_in, const int* in_sizes, int n_in,
                              void* d_out, int out_size) {
    const float* origins = (const float*)d_in[0];
    const float* dirs    = (const float*)d_in[1];
    const float* nearp   = (const float*)d_in[2];
    const float* farp    = (const float*)d_in[3];
    const float* W0 = (const float*)d_in[4];
    const float* b0 = (const float*)d_in[5];
    const float* W1 = (const float*)d_in[6];
    const float* b1 = (const float*)d_in[7];
    const float* W2 = (const float*)d_in[8];
    const float* b2 = (const float*)d_in[9];
    const float* W3 = (const float*)d_in[10];
    const float* b3 = (const float*)d_in[11];
    float* out = (float*)d_out;

    cudaFuncSetAttribute(nerf_fused_kernel,
                         cudaFuncAttributeMaxDynamicSharedMemorySize, SMEM_BYTES);

    int rays = in_sizes[0] / 3;   // 2048
    nerf_fused_kernel<<<rays, THREADS, SMEM_BYTES>>>(
        origins, dirs, nearp, farp, W0, b0, W1, b1, W2, b2, W3, b3, out);
}

// round 4
// speedup vs baseline: 1.0007x; 1.0007x over previous
#include <cuda_runtime.h>
#include <cstdint>

#define THREADS 256
#define HID 256
#define CHUNK 32

#define HS_FLOATS (64 * 256)            // activations
#define WS_FLOATS (2 * CHUNK * 256)     // weight double buffer
#define A0_FLOATS (64 * 64)             // PE input (63 padded to 64), reused as scratch
#define SMEM_BYTES ((HS_FLOATS + WS_FLOATS + A0_FLOATS) * 4)

__device__ __forceinline__ uint32_t sm_u32(const void* p) {
    return (uint32_t)__cvta_generic_to_shared(p);
}

__device__ __forceinline__ void cp_chunk(float* dst, const float* __restrict__ src, int tid) {
    // one CHUNK x 256 fp32 tile = 2048 float4 slots; 8 per thread
#pragma unroll
    for (int s = 0; s < 8; ++s) {
        int slot = tid + s * THREADS;
        asm volatile("cp.async.cg.shared.global [%0], [%1], 16;\n"
                     :: "r"(sm_u32(dst + slot * 4)), "l"(src + slot * 4) : "memory");
    }
}

// M=64 x N=256 register-tiled FMA over one 32-wide K chunk.
// Thread (tm = tid>>5, tn = tid&31) owns rows [tm*8, tm*8+8) and columns
// {tn*4..tn*4+3} U {128+tn*4..128+tn*4+3}  -> conflict-free LDS.128 on W rows,
// warp-uniform (broadcast) LDS.128 on A rows.
template<int AS>
__device__ __forceinline__ void mma_chunk(float (&acc)[8][8],
        const float* __restrict__ A, int kbase,
        const float* __restrict__ Wb, int r0, int n0a, int n0b) {
#pragma unroll
    for (int kk = 0; kk < CHUNK; kk += 4) {
        float4 a4[8];
#pragma unroll
        for (int i = 0; i < 8; ++i)
            a4[i] = *(const float4*)(A + (r0 + i) * AS + kbase + kk);
#pragma unroll
        for (int u = 0; u < 4; ++u) {
            const float* wr = Wb + (kk + u) * HID;
            float4 w0 = *(const float4*)(wr + n0a);
            float4 w1 = *(const float4*)(wr + n0b);
            float wv[8] = {w0.x, w0.y, w0.z, w0.w, w1.x, w1.y, w1.z, w1.w};
#pragma unroll
            for (int i = 0; i < 8; ++i) {
                float av = (u == 0) ? a4[i].x : (u == 1) ? a4[i].y
                         : (u == 2) ? a4[i].z : a4[i].w;
#pragma unroll
                for (int j = 0; j < 8; ++j)
                    acc[i][j] = fmaf(av, wv[j], acc[i][j]);
            }
        }
    }
}

__device__ __forceinline__ void finish_layer(float (&acc)[8][8],
        const float* __restrict__ bg, float* Out, int r0, int n0a, int n0b) {
    float4 bb0 = *(const float4*)(bg + n0a);
    float4 bb1 = *(const float4*)(bg + n0b);
    float bs[8] = {bb0.x, bb0.y, bb0.z, bb0.w, bb1.x, bb1.y, bb1.z, bb1.w};
    __syncthreads();  // all reads of the input activation buffer are done
#pragma unroll
    for (int i = 0; i < 8; ++i) {
        float4 v0, v1;
        v0.x = fmaxf(acc[i][0] + bs[0], 0.f);
        v0.y = fmaxf(acc[i][1] + bs[1], 0.f);
        v0.z = fmaxf(acc[i][2] + bs[2], 0.f);
        v0.w = fmaxf(acc[i][3] + bs[3], 0.f);
        v1.x = fmaxf(acc[i][4] + bs[4], 0.f);
        v1.y = fmaxf(acc[i][5] + bs[5], 0.f);
        v1.z = fmaxf(acc[i][6] + bs[6], 0.f);
        v1.w = fmaxf(acc[i][7] + bs[7], 0.f);
        *(float4*)(Out + (r0 + i) * HID + n0a) = v0;
        *(float4*)(Out + (r0 + i) * HID + n0b) = v1;
    }
    __syncthreads();
}

// 256x256 layer with cp.async double-buffered weight streaming, in-place on Hs.
__device__ __forceinline__ void big_layer(const float* __restrict__ Wg,
        const float* __restrict__ bg, float* Hs, float* Ws,
        int r0, int n0a, int n0b, int tid) {
    float acc[8][8];
#pragma unroll
    for (int i = 0; i < 8; ++i)
#pragma unroll
        for (int j = 0; j < 8; ++j) acc[i][j] = 0.f;

    cp_chunk(Ws, Wg, tid);
    asm volatile("cp.async.commit_group;\n" ::: "memory");
#pragma unroll 1
    for (int c = 0; c < 8; ++c) {
        asm volatile("cp.async.wait_group 0;\n" ::: "memory");
        __syncthreads();                          // chunk c visible to all threads
        if (c < 7) {
            cp_chunk(Ws + ((c + 1) & 1) * (CHUNK * HID),
                     Wg + (c + 1) * (CHUNK * HID), tid);
            asm volatile("cp.async.commit_group;\n" ::: "memory");
        }
        mma_chunk<HID>(acc, Hs, c * CHUNK, Ws + (c & 1) * (CHUNK * HID),
                       r0, n0a, n0b);
    }
    finish_layer(acc, bg, Hs, r0, n0a, n0b);
}

__global__ void __launch_bounds__(THREADS, 1)
nerf_fused_kernel(const float* __restrict__ origins,
                  const float* __restrict__ dirs,
                  const float* __restrict__ nearp,
                  const float* __restrict__ farp,
                  const float* __restrict__ W0, const float* __restrict__ b0,
                  const float* __restrict__ W1, const float* __restrict__ b1,
                  const float* __restrict__ W2, const float* __restrict__ b2,
                  const float* __restrict__ W3, const float* __restrict__ b3,
                  float* __restrict__ out) {
    extern __shared__ float sm[];
    float* Hs  = sm;                           // 64 x 256
    float* Ws  = sm + HS_FLOATS;               // 2 x 32 x 256
    float* A0s = sm + HS_FLOATS + WS_FLOATS;   // 64 x 64 (63 valid + zero pad)

    const int tid = threadIdx.x;
    const int ray = blockIdx.x;
    const int tm = tid >> 5, tn = tid & 31;
    const int r0 = tm * 8;
    const int n0a = tn * 4;
    const int n0b = 128 + tn * 4;

    const float nearv = *nearp, farv = *farp;
    const float step = (farv - nearv) * (1.0f / 64.0f);

    // ---- sample locations (faithful midpoint: b[s] + b[s+1]/2) into A0s cols 0..2
    if (tid < 192) {
        int s = tid / 3, d = tid % 3;
        float bs  = nearv + step * (float)s;
        float bs1 = nearv + step * (float)(s + 1);
        float mid = bs + 0.5f * bs1;
        A0s[s * 64 + d] = origins[ray * 3 + d] + mid * dirs[ray * 3 + d];
    }
    if (tid < 64) A0s[tid * 64 + 63] = 0.f;     // zero pad col 63
    __syncthreads();

    // ---- positional encoding: feature 3 + f*6 + j ; j<3 sin, j>=3 cos, dim = j%3
    for (int idx = tid; idx < 64 * 60; idx += THREADS) {
        int s = idx / 60, e = idx % 60;
        int f = e / 6, j = e % 6;
        float v = A0s[s * 64 + (j % 3)] * exp2f((float)f);
        A0s[s * 64 + 3 + e] = (j < 3) ? sinf(v) : cosf(v);
    }
    __syncthreads();

    // ---- layer 0: A0s[64x64] @ W0[63x256] (row 63 zero-filled)
    {
        float acc[8][8];
#pragma unroll
        for (int i = 0; i < 8; ++i)
#pragma unroll
            for (int j = 0; j < 8; ++j) acc[i][j] = 0.f;
#pragma unroll 1
        for (int c = 0; c < 2; ++c) {
            __syncthreads();
#pragma unroll
            for (int s = 0; s < 8; ++s) {
                int slot = tid + s * THREADS;           // 0..2047
                int row = slot >> 6, col4 = slot & 63;
                int gk = c * CHUNK + row;
                float4 v = make_float4(0.f, 0.f, 0.f, 0.f);
                if (gk < 63) v = *(const float4*)(W0 + gk * HID + col4 * 4);
                *(float4*)(Ws + slot * 4) = v;
            }
            __syncthreads();
            mma_chunk<64>(acc, A0s, c * CHUNK, Ws, r0, n0a, n0b);
        }
        finish_layer(acc, b0, Hs, r0, n0a, n0b);
    }

    // ---- layers 1, 2: 256x256, in-place on Hs
    big_layer(W1, b1, Hs, Ws, r0, n0a, n0b, tid);
    big_layer(W2, b2, Hs, Ws, r0, n0a, n0b, tid);

    // ---- layer 3: Hs[64x256] @ W3[256x4] + b3 -> A0s[0..255] (p*4+c)
    for (int i = tid; i < 1024; i += THREADS) Ws[i] = W3[i];
    __syncthreads();
    {
        int p = tid >> 2, cc = tid & 3;
        float a3 = b3[cc];
        const float* hrow = Hs + p * HID;
#pragma unroll 8
        for (int k = 0; k < HID; k += 4) {
            float4 h4 = *(const float4*)(hrow + k);
            a3 = fmaf(h4.x, Ws[(k + 0) * 4 + cc], a3);
            a3 = fmaf(h4.y, Ws[(k + 1) * 4 + cc], a3);
            a3 = fmaf(h4.z, Ws[(k + 2) * 4 + cc], a3);
            a3 = fmaf(h4.w, Ws[(k + 3) * 4 + cc], a3);
        }
        A0s[tid] = a3;
    }
    __syncthreads();

    // ---- alpha compositing
    float* out4s  = A0s;          // 256 floats
    float* alphas = A0s + 256;    // 64
    float* rgbs   = A0s + 320;    // 192
    if (tid < 64) {
        float sig = fmaxf(out4s[tid * 4 + 3], 0.f);
        float d0 = (nearv + step * (float)(tid + 1)) - (nearv + step * (float)tid);
        alphas[tid] = 1.f - expf(-sig * d0);
    }
    if (tid < 192) {
        int s = tid / 3, c = tid % 3;
        float x = out4s[s * 4 + c];
        rgbs[tid] = 1.f / (1.f + expf(-x));
    }
    __syncthreads();
    if (tid < 3) {
        float T = 1.f, accum = 0.f;
#pragma unroll 1
        for (int s = 0; s < 64; ++s) {
            float a = alphas[s];
            accum += T * a * rgbs[s * 3 + tid];
            T *= (1.f - a);
        }
        out[ray * 3 + tid] = accum;
    }
}

extern "C" void kernel_launch(void* const* d_in, const int* in_sizes, int n_in,
                              void* d_out, int out_size) {
    const float* origins = (const float*)d_in[0];
    const float* dirs    = (const float*)d_in[1];
    const float* nearp   = (const float*)d_in[2];
    const float* farp    = (const float*)d_in[3];
    const float* W0 = (const float*)d_in[4];
    const float* b0 = (const float*)d_in[5];
    const float* W1 = (const float*)d_in[6];
    const float* b1 = (const float*)d_in[7];
    const float* W2 = (const float*)d_in[8];
    const float* b2 = (const float*)d_in[9];
    const float* W3 = (const float*)d_in[10];
    const float* b3 = (const float*)d_in[11];
    float* out = (float*)d_out;

    cudaFuncSetAttribute(nerf_fused_kernel,
                         cudaFuncAttributeMaxDynamicSharedMemorySize, SMEM_BYTES);

    int rays = in_sizes[0] / 3;   // 2048
    nerf_fused_kernel<<<rays, THREADS, SMEM_BYTES>>>(
        origins, dirs, nearp, farp, W0, b0, W1, b1, W2, b2, W3, b3, out);
}

// round 5
// speedup vs baseline: 1.0018x; 1.0011x over previous
#include <cuda_runtime.h>
#include <cstdint>

#define THREADS 256
#define HID 256
#define CHUNK 32

#define HS_FLOATS (64 * 256)            // activations
#define WS_FLOATS (2 * CHUNK * 256)     // weight double buffer
#define A0_FLOATS (64 * 64)             // PE input (63 padded to 64), reused as scratch
#define SMEM_BYTES ((HS_FLOATS + WS_FLOATS + A0_FLOATS) * 4)

__device__ __forceinline__ uint32_t sm_u32(const void* p) {
    return (uint32_t)__cvta_generic_to_shared(p);
}

__device__ __forceinline__ void cp_chunk(float* dst, const float* __restrict__ src, int tid) {
    // one CHUNK x 256 fp32 tile = 2048 float4 slots; 8 per thread
#pragma unroll
    for (int s = 0; s < 8; ++s) {
        int slot = tid + s * THREADS;
        asm volatile("cp.async.cg.shared.global [%0], [%1], 16;\n"
                     :: "r"(sm_u32(dst + slot * 4)), "l"(src + slot * 4) : "memory");
    }
}

// M=64 x N=256 register-tiled FMA over one 32-wide K chunk.
// Thread (tm = tid>>5, tn = tid&31) owns rows [tm*8, tm*8+8) and columns
// {tn*4..tn*4+3} U {128+tn*4..128+tn*4+3}  -> conflict-free LDS.128 on W rows,
// warp-uniform (broadcast) LDS.128 on A rows.
template<int AS>
__device__ __forceinline__ void mma_chunk(float (&acc)[8][8],
        const float* __restrict__ A, int kbase,
        const float* __restrict__ Wb, int r0, int n0a, int n0b) {
#pragma unroll
    for (int kk = 0; kk < CHUNK; kk += 4) {
        float4 a4[8];
#pragma unroll
        for (int i = 0; i < 8; ++i)
            a4[i] = *(const float4*)(A + (r0 + i) * AS + kbase + kk);
#pragma unroll
        for (int u = 0; u < 4; ++u) {
            const float* wr = Wb + (kk + u) * HID;
            float4 w0 = *(const float4*)(wr + n0a);
            float4 w1 = *(const float4*)(wr + n0b);
            float wv[8] = {w0.x, w0.y, w0.z, w0.w, w1.x, w1.y, w1.z, w1.w};
#pragma unroll
            for (int i = 0; i < 8; ++i) {
                float av = (u == 0) ? a4[i].x : (u == 1) ? a4[i].y
                         : (u == 2) ? a4[i].z : a4[i].w;
#pragma unroll
                for (int j = 0; j < 8; ++j)
                    acc[i][j] = fmaf(av, wv[j], acc[i][j]);
            }
        }
    }
}

__device__ __forceinline__ void finish_layer(float (&acc)[8][8],
        const float* __restrict__ bg, float* Out, int r0, int n0a, int n0b) {
    float4 bb0 = *(const float4*)(bg + n0a);
    float4 bb1 = *(const float4*)(bg + n0b);
    float bs[8] = {bb0.x, bb0.y, bb0.z, bb0.w, bb1.x, bb1.y, bb1.z, bb1.w};
    __syncthreads();  // all reads of the input activation buffer are done
#pragma unroll
    for (int i = 0; i < 8; ++i) {
        float4 v0, v1;
        v0.x = fmaxf(acc[i][0] + bs[0], 0.f);
        v0.y = fmaxf(acc[i][1] + bs[1], 0.f);
        v0.z = fmaxf(acc[i][2] + bs[2], 0.f);
        v0.w = fmaxf(acc[i][3] + bs[3], 0.f);
        v1.x = fmaxf(acc[i][4] + bs[4], 0.f);
        v1.y = fmaxf(acc[i][5] + bs[5], 0.f);
        v1.z = fmaxf(acc[i][6] + bs[6], 0.f);
        v1.w = fmaxf(acc[i][7] + bs[7], 0.f);
        *(float4*)(Out + (r0 + i) * HID + n0a) = v0;
        *(float4*)(Out + (r0 + i) * HID + n0b) = v1;
    }
    __syncthreads();
}

// 256x256 layer with cp.async double-buffered weight streaming, in-place on Hs.
__device__ __forceinline__ void big_layer(const float* __restrict__ Wg,
        const float* __restrict__ bg, float* Hs, float* Ws,
        int r0, int n0a, int n0b, int tid) {
    float acc[8][8];
#pragma unroll
    for (int i = 0; i < 8; ++i)
#pragma unroll
        for (int j = 0; j < 8; ++j) acc[i][j] = 0.f;

    cp_chunk(Ws, Wg, tid);
    asm volatile("cp.async.commit_group;\n" ::: "memory");
#pragma unroll 1
    for (int c = 0; c < 8; ++c) {
        asm volatile("cp.async.wait_group 0;\n" ::: "memory");
        __syncthreads();                          // chunk c visible to all threads
        if (c < 7) {
            cp_chunk(Ws + ((c + 1) & 1) * (CHUNK * HID),
                     Wg + (c + 1) * (CHUNK * HID), tid);
            asm volatile("cp.async.commit_group;\n" ::: "memory");
        }
        mma_chunk<HID>(acc, Hs, c * CHUNK, Ws + (c & 1) * (CHUNK * HID),
                       r0, n0a, n0b);
    }
    finish_layer(acc, bg, Hs, r0, n0a, n0b);
}

__global__ void __launch_bounds__(THREADS, 1)
nerf_fused_kernel(const float* __restrict__ origins,
                  const float* __restrict__ dirs,
                  const float* __restrict__ nearp,
                  const float* __restrict__ farp,
                  const float* __restrict__ W0, const float* __restrict__ b0,
                  const float* __restrict__ W1, const float* __restrict__ b1,
                  const float* __restrict__ W2, const float* __restrict__ b2,
                  const float* __restrict__ W3, const float* __restrict__ b3,
                  float* __restrict__ out) {
    extern __shared__ float sm[];
    float* Hs  = sm;                           // 64 x 256
    float* Ws  = sm + HS_FLOATS;               // 2 x 32 x 256
    float* A0s = sm + HS_FLOATS + WS_FLOATS;   // 64 x 64 (63 valid + zero pad)

    const int tid = threadIdx.x;
    const int ray = blockIdx.x;
    const int tm = tid >> 5, tn = tid & 31;
    const int r0 = tm * 8;
    const int n0a = tn * 4;
    const int n0b = 128 + tn * 4;

    const float nearv = *nearp, farv = *farp;
    const float step = (farv - nearv) * (1.0f / 64.0f);

    // ---- sample locations (faithful midpoint: b[s] + b[s+1]/2) into A0s cols 0..2
    if (tid < 192) {
        int s = tid / 3, d = tid % 3;
        float bs  = nearv + step * (float)s;
        float bs1 = nearv + step * (float)(s + 1);
        float mid = bs + 0.5f * bs1;
        A0s[s * 64 + d] = origins[ray * 3 + d] + mid * dirs[ray * 3 + d];
    }
    if (tid < 64) A0s[tid * 64 + 63] = 0.f;     // zero pad col 63
    __syncthreads();

    // ---- positional encoding: feature 3 + f*6 + j ; j<3 sin, j>=3 cos, dim = j%3
    for (int idx = tid; idx < 64 * 60; idx += THREADS) {
        int s = idx / 60, e = idx % 60;
        int f = e / 6, j = e % 6;
        float v = A0s[s * 64 + (j % 3)] * exp2f((float)f);
        A0s[s * 64 + 3 + e] = (j < 3) ? sinf(v) : cosf(v);
    }
    __syncthreads();

    // ---- layer 0: A0s[64x64] @ W0[63x256] (row 63 zero-filled)
    {
        float acc[8][8];
#pragma unroll
        for (int i = 0; i < 8; ++i)
#pragma unroll
            for (int j = 0; j < 8; ++j) acc[i][j] = 0.f;
#pragma unroll 1
        for (int c = 0; c < 2; ++c) {
            __syncthreads();
#pragma unroll
            for (int s = 0; s < 8; ++s) {
                int slot = tid + s * THREADS;           // 0..2047
                int row = slot >> 6, col4 = slot & 63;
                int gk = c * CHUNK + row;
                float4 v = make_float4(0.f, 0.f, 0.f, 0.f);
                if (gk < 63) v = *(const float4*)(W0 + gk * HID + col4 * 4);
                *(float4*)(Ws + slot * 4) = v;
            }
            __syncthreads();
            mma_chunk<64>(acc, A0s, c * CHUNK, Ws, r0, n0a, n0b);
        }
        finish_layer(acc, b0, Hs, r0, n0a, n0b);
    }

    // ---- layers 1, 2: 256x256, in-place on Hs
    big_layer(W1, b1, Hs, Ws, r0, n0a, n0b, tid);
    big_layer(W2, b2, Hs, Ws, r0, n0a, n0b, tid);

    // ---- layer 3: Hs[64x256] @ W3[256x4] + b3 -> A0s[0..255] (p*4+c)
    for (int i = tid; i < 1024; i += THREADS) Ws[i] = W3[i];
    __syncthreads();
    {
        int p = tid >> 2, cc = tid & 3;
        float a3 = b3[cc];
        const float* hrow = Hs + p * HID;
#pragma unroll 8
        for (int k = 0; k < HID; k += 4) {
            float4 h4 = *(const float4*)(hrow + k);
            a3 = fmaf(h4.x, Ws[(k + 0) * 4 + cc], a3);
            a3 = fmaf(h4.y, Ws[(k + 1) * 4 + cc], a3);
            a3 = fmaf(h4.z, Ws[(k + 2) * 4 + cc], a3);
            a3 = fmaf(h4.w, Ws[(k + 3) * 4 + cc], a3);
        }
        A0s[tid] = a3;
    }
    __syncthreads();

    // ---- alpha compositing
    float* out4s  = A0s;          // 256 floats
    float* alphas = A0s + 256;    // 64
    float* rgbs   = A0s + 320;    // 192
    if (tid < 64) {
        float sig = fmaxf(out4s[tid * 4 + 3], 0.f);
        float d0 = (nearv + step * (float)(tid + 1)) - (nearv + step * (float)tid);
        alphas[tid] = 1.f - expf(-sig * d0);
    }
    if (tid < 192) {
        int s = tid / 3, c = tid % 3;
        float x = out4s[s * 4 + c];
        rgbs[tid] = 1.f / (1.f + expf(-x));
    }
    __syncthreads();
    if (tid < 3) {
        float T = 1.f, accum = 0.f;
#pragma unroll 1
        for (int s = 0; s < 64; ++s) {
            float a = alphas[s];
            accum += T * a * rgbs[s * 3 + tid];
            T *= (1.f - a);
        }
        out[ray * 3 + tid] = accum;
    }
}

extern "C" void kernel_launch(void* const* d_in, const int* in_sizes, int n_in,
                              void* d_out, int out_size) {
    const float* origins = (const float*)d_in[0];
    const float* dirs    = (const float*)d_in[1];
    const float* nearp   = (const float*)d_in[2];
    const float* farp    = (const float*)d_in[3];
    const float* W0 = (const float*)d_in[4];
    const float* b0 = (const float*)d_in[5];
    const float* W1 = (const float*)d_in[6];
    const float* b1 = (const float*)d_in[7];
    const float* W2 = (const float*)d_in[8];
    const float* b2 = (const float*)d_in[9];
    const float* W3 = (const float*)d_in[10];
    const float* b3 = (const float*)d_in[11];
    float* out = (float*)d_out;

    cudaFuncSetAttribute(nerf_fused_kernel,
                         cudaFuncAttributeMaxDynamicSharedMemorySize, SMEM_BYTES);

    int rays = in_sizes[0] / 3;   // 2048
    nerf_fused_kernel<<<rays, THREADS, SMEM_BYTES>>>(
        origins, dirs, nearp, farp, W0, b0, W1, b1, W2, b2, W3, b3, out);
}